// round 14
// baseline (speedup 1.0000x reference)
#include <cuda_runtime.h>
#include <cuda_fp16.h>

#define B_DIM 2048
#define IN_DIM 8192
#define O_DIM 4096
#define K_DIM 64

// 32 MB transposed fp16 copy of x: xth[i][b] (b contiguous, L2-resident)
__device__ __half g_xth[(size_t)IN_DIM * B_DIM];

// ---------------------------------------------------------------------------
// Kernel 1: transpose+convert x[B, IN] f32 -> g_xth[IN, B] f16.
// R11 version (measured ~12us, near the 96MB DRAM/LTS floor). Unchanged.
// ---------------------------------------------------------------------------
#define TPITCH 76

__global__ __launch_bounds__(256) void transpose_kernel(const float* __restrict__ x) {
    __shared__ __half2 st2[32][TPITCH];
    const int i0 = blockIdx.x * 64;
    const int b0 = blockIdx.y * 64;
    const int t = threadIdx.x;

    {
        const int r = t >> 2;
        const int c = t & 3;
        const float4* __restrict__ xr = (const float4*)(x + (size_t)(b0 + r) * IN_DIM + i0);
#pragma unroll
        for (int j = 0; j < 4; j++) {
            const float4 f = xr[c + 4 * j];
            const int i2 = 2 * c + 8 * j;
            st2[i2 + 0][r] = __floats2half2_rn(f.x, f.y);
            st2[i2 + 1][r] = __floats2half2_rn(f.z, f.w);
        }
    }
    __syncthreads();
    {
        const int p2 = t >> 4;
        const int m = t & 15;
        const int bb = 4 * m;
#pragma unroll
        for (int pp = 0; pp < 2; pp++) {
            const int p = 2 * p2 + pp;
            const uint4 u = *(const uint4*)&st2[p][bb];
            unsigned int lo0 = __byte_perm(u.x, u.y, 0x5410);
            unsigned int lo1 = __byte_perm(u.z, u.w, 0x5410);
            unsigned int hi0 = __byte_perm(u.x, u.y, 0x7632);
            unsigned int hi1 = __byte_perm(u.z, u.w, 0x7632);
            __half* __restrict__ row0 = g_xth + (size_t)(i0 + 2 * p + 0) * B_DIM + b0 + bb;
            __half* __restrict__ row1 = g_xth + (size_t)(i0 + 2 * p + 1) * B_DIM + b0 + bb;
            *(uint2*)row0 = make_uint2(lo0, lo1);
            *(uint2*)row1 = make_uint2(hi0, hi1);
        }
    }
}

// ---------------------------------------------------------------------------
// Kernel 2: gather + weighted reduce.
// R13 structure (OT=4, grid 1024, thread owns 8 b) + issue diet:
//  - w staged as pre-duplicated half2 (w|w) -> inner (k,j) is
//    LDS.64 + LDG.128 + 4 HFMA2 (was 8 FFMA + 4 cvt).
//  - fp16 partial flushed to fp32 every 4 k (R12 measured this accumulation
//    pattern at rel_err 2.93e-4; budget 1e-3).
//  - fewer live regs -> launch_bounds(256,5): 5 CTAs/SM, 740 resident,
//    occ ~52%, 1.38 waves.
// ---------------------------------------------------------------------------
#define OT 4
#define NTHR 256

__global__ __launch_bounds__(NTHR, 5) void gather_kernel(const int* __restrict__ indices,
                                                         const float* __restrict__ weight,
                                                         const float* __restrict__ bias,
                                                         float* __restrict__ out) {
    __shared__ int2 s_iw[OT * K_DIM];  // 2 KB: {premultiplied row offset, w|w half2 bits}

    const int tid = threadIdx.x;
    const int obase = blockIdx.y * OT;
    const int brow = tid * 8;  // first of this thread's 8 b's

    // Stage refs: one int2 per thread (OT*K == NTHR). w duplicated into half2.
    {
        int2 iw;
        iw.x = indices[(size_t)obase * K_DIM + tid] * (B_DIM / 8);
        const unsigned int hw =
            __half_as_ushort(__float2half(weight[(size_t)obase * K_DIM + tid]));
        iw.y = (int)((hw << 16) | hw);
        s_iw[tid] = iw;
    }
    __syncthreads();

    const uint4* __restrict__ xt8 = (const uint4*)g_xth;

    float facc[OT][8];
#pragma unroll
    for (int j = 0; j < OT; j++)
#pragma unroll
        for (int q = 0; q < 8; q++) facc[j][q] = 0.f;

    for (int kb = 0; kb < K_DIM; kb += 4) {
#pragma unroll
        for (int j = 0; j < OT; j++) {
            __half2 h0 = __floats2half2_rn(0.f, 0.f);
            __half2 h1 = h0, h2 = h0, h3 = h0;
#pragma unroll
            for (int kk = 0; kk < 4; kk++) {
                const int2 iw = s_iw[j * K_DIM + kb + kk];  // one LDS.64 (warp-uniform)
                const __half2 wh = *(const __half2*)&iw.y;
                const uint4 v = xt8[iw.x + tid];            // 8 halves, coalesced along b
                const __half2* h = (const __half2*)&v;
                h0 = __hfma2(h[0], wh, h0);
                h1 = __hfma2(h[1], wh, h1);
                h2 = __hfma2(h[2], wh, h2);
                h3 = __hfma2(h[3], wh, h3);
            }
            // flush 4-term fp16 partials into fp32 accumulators
            const float2 f0 = __half22float2(h0);
            const float2 f1 = __half22float2(h1);
            const float2 f2 = __half22float2(h2);
            const float2 f3 = __half22float2(h3);
            facc[j][0] += f0.x; facc[j][1] += f0.y;
            facc[j][2] += f1.x; facc[j][3] += f1.y;
            facc[j][4] += f2.x; facc[j][5] += f2.y;
            facc[j][6] += f3.x; facc[j][7] += f3.y;
        }
    }

    float bv[OT];
#pragma unroll
    for (int j = 0; j < OT; j++) bv[j] = bias[obase + j];

    // Full-width stores: out[b][obase..obase+3] as one STG.128 per b
#pragma unroll
    for (int bb = 0; bb < 8; bb++) {
        float4 v;
        v.x = facc[0][bb] + bv[0];
        v.y = facc[1][bb] + bv[1];
        v.z = facc[2][bb] + bv[2];
        v.w = facc[3][bb] + bv[3];
        *(float4*)(out + (size_t)(brow + bb) * O_DIM + obase) = v;
    }
}

// ---------------------------------------------------------------------------
// Launch
// ---------------------------------------------------------------------------
extern "C" void kernel_launch(void* const* d_in, const int* in_sizes, int n_in,
                              void* d_out, int out_size) {
    (void)in_sizes; (void)n_in; (void)out_size;
    const float* x = (const float*)d_in[0];
    const int* indices = (const int*)d_in[1];
    const float* weight = (const float*)d_in[2];
    const float* bias = (const float*)d_in[3];
    float* out = (float*)d_out;

    dim3 tg(IN_DIM / 64, B_DIM / 64);  // (128, 32)
    transpose_kernel<<<tg, 256>>>(x);

    dim3 gg(1, O_DIM / OT);  // (1, 1024)
    gather_kernel<<<gg, NTHR>>>(indices, weight, bias, out);
}

// round 15
// speedup vs baseline: 1.2823x; 1.2823x over previous
#include <cuda_runtime.h>
#include <cuda_fp16.h>

#define B_DIM 2048
#define IN_DIM 8192
#define O_DIM 4096
#define K_DIM 64

// 32 MB transposed fp16 copy of x: xth[i][b] (b contiguous, L2-resident)
__device__ __half g_xth[(size_t)IN_DIM * B_DIM];

// ---------------------------------------------------------------------------
// Kernel 1: transpose+convert x[B, IN] f32 -> g_xth[IN, B] f16.
// R11 version (measured ~12us, near the 96MB DRAM/LTS floor). Unchanged.
// ---------------------------------------------------------------------------
#define TPITCH 76

__global__ __launch_bounds__(256) void transpose_kernel(const float* __restrict__ x) {
    __shared__ __half2 st2[32][TPITCH];
    const int i0 = blockIdx.x * 64;
    const int b0 = blockIdx.y * 64;
    const int t = threadIdx.x;

    {
        const int r = t >> 2;
        const int c = t & 3;
        const float4* __restrict__ xr = (const float4*)(x + (size_t)(b0 + r) * IN_DIM + i0);
#pragma unroll
        for (int j = 0; j < 4; j++) {
            const float4 f = xr[c + 4 * j];
            const int i2 = 2 * c + 8 * j;
            st2[i2 + 0][r] = __floats2half2_rn(f.x, f.y);
            st2[i2 + 1][r] = __floats2half2_rn(f.z, f.w);
        }
    }
    __syncthreads();
    {
        const int p2 = t >> 4;
        const int m = t & 15;
        const int bb = 4 * m;
#pragma unroll
        for (int pp = 0; pp < 2; pp++) {
            const int p = 2 * p2 + pp;
            const uint4 u = *(const uint4*)&st2[p][bb];
            unsigned int lo0 = __byte_perm(u.x, u.y, 0x5410);
            unsigned int lo1 = __byte_perm(u.z, u.w, 0x5410);
            unsigned int hi0 = __byte_perm(u.x, u.y, 0x7632);
            unsigned int hi1 = __byte_perm(u.z, u.w, 0x7632);
            __half* __restrict__ row0 = g_xth + (size_t)(i0 + 2 * p + 0) * B_DIM + b0 + bb;
            __half* __restrict__ row1 = g_xth + (size_t)(i0 + 2 * p + 1) * B_DIM + b0 + bb;
            *(uint2*)row0 = make_uint2(lo0, lo1);
            *(uint2*)row1 = make_uint2(hi0, hi1);
        }
    }
}

// ---------------------------------------------------------------------------
// Kernel 2: gather + weighted reduce (fp16 xt, fp32 FFMA accumulate).
// R13 base (best: gather 85.2us, L1=78.6% = binding pipe) with the L1
// metadata cycles halved: refs staged as PAIRED int4
// {off_2k, w_2k, off_2k+1, w_2k+1} -> one LDS.128 serves two k iterations
// (was one LDS.64 per iteration). regs kept ~64 (launch_bounds(256,4)):
// R14 proved squeezing regs kills per-warp MLP and loses more than occ gains.
// Thread owns 8 consecutive b; grid (1,1024); 8 LDG.128 batched per body.
// ---------------------------------------------------------------------------
#define OT 4
#define NTHR 256
#define K2 (K_DIM / 2)

__global__ __launch_bounds__(NTHR, 4) void gather_kernel(const int* __restrict__ indices,
                                                         const float* __restrict__ weight,
                                                         const float* __restrict__ bias,
                                                         float* __restrict__ out) {
    __shared__ int4 s_iw4[OT * K2];  // 2 KB: paired {off,w,off,w}

    const int tid = threadIdx.x;
    const int obase = blockIdx.y * OT;
    const int brow = tid * 8;  // first of this thread's 8 b's

    // Stage paired refs: threads 0..127 build one int4 each (OT*K2 == 128).
    if (tid < OT * K2) {
        const int j = tid >> 5;        // o_local (K2 == 32)
        const int k2 = tid & 31;
        const size_t base = (size_t)(obase + j) * K_DIM + 2 * k2;
        int4 p;
        p.x = indices[base + 0] * (B_DIM / 8);
        p.y = __float_as_int(weight[base + 0]);
        p.z = indices[base + 1] * (B_DIM / 8);
        p.w = __float_as_int(weight[base + 1]);
        s_iw4[j * K2 + k2] = p;
    }
    __syncthreads();

    const uint4* __restrict__ xt8 = (const uint4*)g_xth;

    float acc[OT][8];
#pragma unroll
    for (int j = 0; j < OT; j++)
#pragma unroll
        for (int q = 0; q < 8; q++) acc[j][q] = 0.f;

#pragma unroll 2
    for (int k2 = 0; k2 < K2; k2++) {
#pragma unroll
        for (int j = 0; j < OT; j++) {
            const int4 p = s_iw4[j * K2 + k2];  // one LDS.128 = 2 k-iters of refs
            const float wA = __int_as_float(p.y);
            const float wB = __int_as_float(p.w);
            const uint4 vA = xt8[p.x + tid];    // 8 halves, coalesced along b
            const uint4 vB = xt8[p.z + tid];
            const __half2* hA = (const __half2*)&vA;
            const __half2* hB = (const __half2*)&vB;
#pragma unroll
            for (int q = 0; q < 4; q++) {
                const float2 fA = __half22float2(hA[q]);
                const float2 fB = __half22float2(hB[q]);
                acc[j][2 * q + 0] += fA.x * wA;
                acc[j][2 * q + 1] += fA.y * wA;
                acc[j][2 * q + 0] += fB.x * wB;
                acc[j][2 * q + 1] += fB.y * wB;
            }
        }
    }

    float bv[OT];
#pragma unroll
    for (int j = 0; j < OT; j++) bv[j] = bias[obase + j];

    // Full-width stores: out[b][obase..obase+3] as one STG.128 per b
#pragma unroll
    for (int bb = 0; bb < 8; bb++) {
        float4 v;
        v.x = acc[0][bb] + bv[0];
        v.y = acc[1][bb] + bv[1];
        v.z = acc[2][bb] + bv[2];
        v.w = acc[3][bb] + bv[3];
        *(float4*)(out + (size_t)(brow + bb) * O_DIM + obase) = v;
    }
}

// ---------------------------------------------------------------------------
// Launch
// ---------------------------------------------------------------------------
extern "C" void kernel_launch(void* const* d_in, const int* in_sizes, int n_in,
                              void* d_out, int out_size) {
    (void)in_sizes; (void)n_in; (void)out_size;
    const float* x = (const float*)d_in[0];
    const int* indices = (const int*)d_in[1];
    const float* weight = (const float*)d_in[2];
    const float* bias = (const float*)d_in[3];
    float* out = (float*)d_out;

    dim3 tg(IN_DIM / 64, B_DIM / 64);  // (128, 32)
    transpose_kernel<<<tg, 256>>>(x);

    dim3 gg(1, O_DIM / OT);  // (1, 1024)
    gather_kernel<<<gg, NTHR>>>(indices, weight, bias, out);
}